// round 5
// baseline (speedup 1.0000x reference)
#include <cuda_runtime.h>

#define HH 50
#define TT 96
#define NPRED 12
#define NTH 256
#define EPB 7          // elements per block
#define KLO_CNT 24     // K-split: [0,24) and [24,50) — both even, 16B-aligned
#define KHI_CNT 26
#define KHI_BASE 24

typedef unsigned long long u64;

__device__ __forceinline__ u64 pk2(float lo, float hi) {
    u64 r; asm("mov.b64 %0, {%1,%2};" : "=l"(r) : "f"(lo), "f"(hi)); return r;
}
__device__ __forceinline__ void upk2(u64 v, float &lo, float &hi) {
    asm("mov.b64 {%0,%1}, %2;" : "=f"(lo), "=f"(hi) : "l"(v));
}
__device__ __forceinline__ u64 ffma2(u64 a, u64 b, u64 c) {
    u64 d; asm("fma.rn.f32x2 %0, %1, %2, %3;" : "=l"(d) : "l"(a), "l"(b), "l"(c)); return d;
}
__device__ __forceinline__ u64 add2(u64 a, u64 b) {
    u64 d; asm("add.rn.f32x2 %0, %1, %2;" : "=l"(d) : "l"(a), "l"(b)); return d;
}
__device__ __forceinline__ float ftanh(float x) {
    float y; asm("tanh.approx.f32 %0, %1;" : "=f"(y) : "f"(x)); return y;
}
__device__ __forceinline__ float fsig(float x) {
    return fmaf(0.5f, ftanh(0.5f * x), 0.5f);
}
__device__ __forceinline__ void esbar(int id) {
    asm volatile("bar.sync %0, 128;" :: "r"(id) : "memory");
}

// Shared state (one block per SM; static shared ~16KB)
// s_hd[e][buf][k] holds (h[k], h[k]) duplicated as u64 for f32x2 operand reuse.
struct SmemT {
    u64        hd[EPB][2][HH];          // 7*2*50*8   = 5600 B (16B-aligned slices)
    ulonglong2 part[EPB][HH];           // 7*50*16    = 5600 B  partial (IF, GO) pairs
    float      win[EPB][TT + NPRED];    //             3024 B  sliding input windows
    float      red[EPB][HH];            //             1400 B  fc reduction
};

// One ES-domain worker. NE = elements in this set, KCNT/KB = this subunit's K slice,
// NOWN = elements this subunit updates (klo owns first 2, khi owns the rest).
template<int NE, int KCNT, int KB, int NOWN>
__device__ __forceinline__ void run_es(
    SmemT* sm, int esbase, int barid, int j, int b0, int B,
    const float* __restrict__ x, const float* __restrict__ W_ih,
    const float* __restrict__ W_hh, const float* __restrict__ b_ih,
    const float* __restrict__ b_hh, const float* __restrict__ W_fc,
    const float* __restrict__ b_fc, float* __restrict__ out)
{
    constexpr bool KLOW = (KB == 0);
    constexpr int  OWN_OFF = KLOW ? 0 : 2;           // local index of first owned elem
    const int jr = (j < HH) ? j : (HH - 1);          // clamp for safe loads

    // Weights: gate-pair packed. wIF[k]=(Wi[j][KB+k],Wf[j][KB+k]), wGO likewise.
    u64 wIF[KCNT], wGO[KCNT];
#pragma unroll
    for (int k = 0; k < KCNT; k++) {
        wIF[k] = pk2(W_hh[(0 * HH + jr) * HH + KB + k], W_hh[(1 * HH + jr) * HH + KB + k]);
        wGO[k] = pk2(W_hh[(2 * HH + jr) * HH + KB + k], W_hh[(3 * HH + jr) * HH + KB + k]);
    }
    u64 xwIF = 0, xwGO = 0, bIF = 0, bGO = 0;
    if (KLOW) {  // x-term + bias folded only by the K-low subunit (avoid double count)
        xwIF = pk2(W_ih[jr], W_ih[HH + jr]);
        xwGO = pk2(W_ih[2 * HH + jr], W_ih[3 * HH + jr]);
        bIF  = pk2(b_ih[jr] + b_hh[jr],           b_ih[HH + jr] + b_hh[HH + jr]);
        bGO  = pk2(b_ih[2 * HH + jr] + b_hh[2 * HH + jr],
                   b_ih[3 * HH + jr] + b_hh[3 * HH + jr]);
    }
    const float wfc = W_fc[jr];
    const float bfc = b_fc[0];

    for (int p = 0; p < NPRED; p++) {
        // zero read-buffer 0 for owned elements; reset cell state
        if (j < HH) {
#pragma unroll
            for (int oi = 0; oi < NOWN; oi++)
                sm->hd[esbase + OWN_OFF + oi][0][j] = 0ull;
        }
        float cst[NOWN], hn[NOWN];
#pragma unroll
        for (int oi = 0; oi < NOWN; oi++) { cst[oi] = 0.0f; hn[oi] = 0.0f; }
        esbar(barid);

#pragma unroll 1
        for (int t = 0; t < TT; t++) {
            const int buf = t & 1;
            u64 aIF[NE], aGO[NE];
#pragma unroll
            for (int e = 0; e < NE; e++) {
                if (KLOW) {
                    const float xt = sm->win[esbase + e][p + t];
                    const u64 xd = pk2(xt, xt);
                    aIF[e] = ffma2(xd, xwIF, bIF);
                    aGO[e] = ffma2(xd, xwGO, bGO);
                } else {
                    aIF[e] = 0ull; aGO[e] = 0ull;
                }
            }
#pragma unroll
            for (int np = 0; np < KCNT / 2; np++) {
#pragma unroll
                for (int e = 0; e < NE; e++) {
                    ulonglong2 hv = *reinterpret_cast<const ulonglong2*>(
                        &sm->hd[esbase + e][buf][KB + 2 * np]);   // broadcast LDS.128
                    aIF[e] = ffma2(wIF[2 * np], hv.x, aIF[e]);
                    aGO[e] = ffma2(wGO[2 * np], hv.x, aGO[e]);
                    aIF[e] = ffma2(wIF[2 * np + 1], hv.y, aIF[e]);
                    aGO[e] = ffma2(wGO[2 * np + 1], hv.y, aGO[e]);
                }
            }
            // export partials for elements the OTHER subunit owns
            if (j < HH) {
#pragma unroll
                for (int le = 0; le < NE; le++) {
                    const bool foreign = KLOW ? (le >= 2) : (le < 2);
                    if (foreign) {
                        ulonglong2 v; v.x = aIF[le]; v.y = aGO[le];
                        sm->part[esbase + le][j] = v;
                    }
                }
            }
            esbar(barid);
            if (j < HH) {
#pragma unroll
                for (int oi = 0; oi < NOWN; oi++) {
                    const int le = OWN_OFF + oi;
                    ulonglong2 pf = sm->part[esbase + le][j];
                    u64 gIF = add2(aIF[le], pf.x);
                    u64 gGO = add2(aGO[le], pf.y);
                    float gi, gf, gg, go;
                    upk2(gIF, gi, gf);
                    upk2(gGO, gg, go);
                    const float i_ = fsig(gi);
                    const float f_ = fsig(gf);
                    const float g_ = ftanh(gg);
                    const float o_ = fsig(go);
                    cst[oi] = fmaf(f_, cst[oi], i_ * g_);
                    hn[oi]  = o_ * ftanh(cst[oi]);
                    sm->hd[esbase + le][buf ^ 1][j] = pk2(hn[oi], hn[oi]);
                }
            }
            esbar(barid);
        }

        // FC head: out = h . W_fc + b_fc, then slide window
        if (j < HH) {
#pragma unroll
            for (int oi = 0; oi < NOWN; oi++)
                sm->red[esbase + OWN_OFF + oi][j] = hn[oi] * wfc;
        }
        esbar(barid);
        if (j < NOWN) {
            const int e = esbase + OWN_OFF + j;
            float s = bfc;
#pragma unroll
            for (int k = 0; k < HH; k++) s += sm->red[e][k];
            sm->win[e][TT + p] = s;
            if (b0 + e < B) out[(b0 + e) * NPRED + p] = s;
        }
        esbar(barid);
    }
}

__global__ __launch_bounds__(NTH, 1)
void lstm_recursive_kernel(const float* __restrict__ x,
                           const float* __restrict__ W_ih,
                           const float* __restrict__ W_hh,
                           const float* __restrict__ b_ih,
                           const float* __restrict__ b_hh,
                           const float* __restrict__ W_fc,
                           const float* __restrict__ b_fc,
                           float* __restrict__ out, int B) {
    __shared__ __align__(16) SmemT sm;
    const int su = threadIdx.x >> 6;   // subunit 0..3 (64 lanes each)
    const int j  = threadIdx.x & 63;
    const int b0 = blockIdx.x * EPB;

    // fill the 7 input windows (clamp dummy elements to B-1)
    for (int idx = threadIdx.x; idx < EPB * TT; idx += NTH) {
        const int le = idx / TT, tp = idx % TT;
        int src = b0 + le; if (src > B - 1) src = B - 1;
        sm.win[le][tp] = x[src * TT + tp];
    }
    __syncthreads();

    // su0: K-lo of es0{0..3}, owns {0,1}   su3: K-hi of es0, owns {2,3}
    // su1: K-lo of es1{4..6}, owns {4,5}   su2: K-hi of es1, owns {6}
    // SMSP pairing (wid%4): each SMSP gets one es0-warp + one es1-warp -> balanced + staggered.
    if (su == 0)
        run_es<4, KLO_CNT, 0,        2>(&sm, 0, 1, j, b0, B, x, W_ih, W_hh, b_ih, b_hh, W_fc, b_fc, out);
    else if (su == 1)
        run_es<3, KLO_CNT, 0,        2>(&sm, 4, 2, j, b0, B, x, W_ih, W_hh, b_ih, b_hh, W_fc, b_fc, out);
    else if (su == 2)
        run_es<3, KHI_CNT, KHI_BASE, 1>(&sm, 4, 2, j, b0, B, x, W_ih, W_hh, b_ih, b_hh, W_fc, b_fc, out);
    else
        run_es<4, KHI_CNT, KHI_BASE, 2>(&sm, 0, 1, j, b0, B, x, W_ih, W_hh, b_ih, b_hh, W_fc, b_fc, out);
}

extern "C" void kernel_launch(void* const* d_in, const int* in_sizes, int n_in,
                              void* d_out, int out_size) {
    const float* x    = (const float*)d_in[0];
    const float* W_ih = (const float*)d_in[1];
    const float* W_hh = (const float*)d_in[2];
    const float* b_ih = (const float*)d_in[3];
    const float* b_hh = (const float*)d_in[4];
    const float* W_fc = (const float*)d_in[5];
    const float* b_fc = (const float*)d_in[6];
    float* out = (float*)d_out;

    const int B = out_size / NPRED;                 // 1024
    const int grid = (B + EPB - 1) / EPB;           // 147
    lstm_recursive_kernel<<<grid, NTH>>>(x, W_ih, W_hh, b_ih, b_hh, W_fc, b_fc, out, B);
}